// round 1
// baseline (speedup 1.0000x reference)
#include <cuda_runtime.h>
#include <cuda_bf16.h>
#include <cstdint>

// Shifted-window attention block: B=16, H=W=112, C=192, heads=6, hd=32, WS=7, SHIFT=3.
// 112 % 7 == 0 -> no padding; roll+partition is a permutation of tokens into
// 4096 windows x 49 tokens. One CTA per window, rows padded to 64.

#define CHN   192
#define LWIN  49
#define LPAD  64
#define NHEADS 6
#define HDIM  32
#define HWDIM 112
#define NPIX  (112*112)
#define NWIN  4096
#define XP    200    // xs pitch (bf16 elems): 400B/row -> conflict-free frag loads
#define QP    584    // qkv pitch
#define WP    200    // weight-stage pitch

// ---- persistent bf16 weight copies (converted once per launch) ----
__device__ __nv_bfloat16 g_wqkv[576 * 192];
__device__ __nv_bfloat16 g_wout[192 * 192];

__global__ void prep_weights(const float* __restrict__ wqkv,
                             const float* __restrict__ wout) {
    int i = blockIdx.x * 256 + threadIdx.x;
    if (i < 576 * 192) g_wqkv[i] = __float2bfloat16(wqkv[i]);
    if (i < 192 * 192) g_wout[i] = __float2bfloat16(wout[i]);
}

__device__ __forceinline__ uint32_t ld_u32(const __nv_bfloat16* p) {
    return *reinterpret_cast<const uint32_t*>(p);
}
__device__ __forceinline__ uint32_t packbf(float a, float b) {
    __nv_bfloat162 t = __floats2bfloat162_rn(a, b);
    return *reinterpret_cast<uint32_t*>(&t);
}
__device__ __forceinline__ void mma_bf16(float* c,
        uint32_t a0, uint32_t a1, uint32_t a2, uint32_t a3,
        uint32_t b0, uint32_t b1) {
    asm volatile(
        "mma.sync.aligned.m16n8k16.row.col.f32.bf16.bf16.f32 "
        "{%0,%1,%2,%3}, {%4,%5,%6,%7}, {%8,%9}, {%0,%1,%2,%3};\n"
        : "+f"(c[0]), "+f"(c[1]), "+f"(c[2]), "+f"(c[3])
        : "r"(a0), "r"(a1), "r"(a2), "r"(a3), "r"(b0), "r"(b1));
}

// smem layout (bytes)
#define OFF_XS   0
#define OFF_QS   25600      // 64*200*2
#define OFF_WS   100352     // + 64*584*2
#define OFF_GAM  125952     // + 64*200*2
#define OFF_BET  126720
#define OFF_BQ   127488
#define OFF_BO   129792
#define OFF_ROW  130560
#define SMEM_BYTES 130816

__global__ __launch_bounds__(256) void swin_kernel(
    const float* __restrict__ x,
    const float* __restrict__ b_qkv,
    const float* __restrict__ b_out,
    const float* __restrict__ gamma,
    const float* __restrict__ beta,
    float* __restrict__ out)
{
    extern __shared__ unsigned char smem[];
    __nv_bfloat16* xs = (__nv_bfloat16*)(smem + OFF_XS);   // 64 x XP: xn, later attn-out
    __nv_bfloat16* qs = (__nv_bfloat16*)(smem + OFF_QS);   // 64 x QP: qkv
    __nv_bfloat16* ws = (__nv_bfloat16*)(smem + OFF_WS);   // 64 x WP: staged weights
    float* s_gam = (float*)(smem + OFF_GAM);
    float* s_bet = (float*)(smem + OFF_BET);
    float* s_bq  = (float*)(smem + OFF_BQ);
    float* s_bo  = (float*)(smem + OFF_BO);
    int*   s_row = (int*)(smem + OFF_ROW);

    const int tid  = threadIdx.x;
    const int warp = tid >> 5, lane = tid & 31;
    const int g  = lane >> 2, tg = lane & 3;
    const int rb = (warp & 3) * 16;        // output row block (16 rows)
    const int cb = (warp >> 2) * 32;       // output col block within 64-chunk

    const int wi = blockIdx.x;
    const int bidx = wi >> 8;
    const int wh = (wi >> 4) & 15;
    const int ww = wi & 15;

    // ---------- phase 0: params + token gather offsets ----------
    if (tid < 192) {
        s_gam[tid] = gamma[tid];
        s_bet[tid] = beta[tid];
        s_bo[tid]  = b_out[tid];
    }
    for (int i = tid; i < 576; i += 256) s_bq[i] = b_qkv[i];
    if (tid < 64) {
        int r = 0;
        if (tid < 49) {
            int ii = tid / 7, jj = tid % 7;
            int hh = wh * 7 + ii + 3; if (hh >= HWDIM) hh -= HWDIM;
            int cc = ww * 7 + jj + 3; if (cc >= HWDIM) cc -= HWDIM;
            r = bidx * NPIX + hh * HWDIM + cc;
        }
        s_row[tid] = r;
    }
    // zero xs pad rows 49..63 (cols 0..191)
    for (int i = tid; i < 15 * 96; i += 256) {
        int row = 49 + i / 96, cw = i % 96;
        ((uint32_t*)(xs + row * XP))[cw] = 0u;
    }
    __syncthreads();

    // ---------- phase 1: gather + LayerNorm -> xs (bf16) ----------
    for (int l = warp; l < LWIN; l += 8) {
        const float* xr = x + (long)s_row[l] * CHN;
        float v[6];
        float sum = 0.f, ssq = 0.f;
#pragma unroll
        for (int j = 0; j < 6; ++j) {
            v[j] = xr[lane + j * 32];
            sum += v[j]; ssq += v[j] * v[j];
        }
#pragma unroll
        for (int o = 16; o > 0; o >>= 1) {
            sum += __shfl_xor_sync(0xffffffffu, sum, o);
            ssq += __shfl_xor_sync(0xffffffffu, ssq, o);
        }
        float mu  = sum * (1.f / 192.f);
        float var = ssq * (1.f / 192.f) - mu * mu;
        float rs  = rsqrtf(var + 1e-5f);
#pragma unroll
        for (int j = 0; j < 6; ++j) {
            int c = lane + j * 32;
            xs[l * XP + c] = __float2bfloat16((v[j] - mu) * rs * s_gam[c] + s_bet[c]);
        }
    }
    __syncthreads();

    // ---------- phase 2: QKV GEMM (64x192)@(192x576) -> qs ----------
#pragma unroll 1
    for (int nc = 0; nc < 9; ++nc) {
        // stage 64 weight rows (n-major, bf16) into ws
        for (int idx = tid; idx < 1536; idx += 256) {
            int row = idx / 24, u = idx % 24;
            ((uint4*)(ws + row * WP))[u] =
                ((const uint4*)(g_wqkv + (nc * 64 + row) * 192))[u];
        }
        __syncthreads();
        float acc[4][4];
#pragma unroll
        for (int nt = 0; nt < 4; ++nt)
#pragma unroll
            for (int e = 0; e < 4; ++e) acc[nt][e] = 0.f;
#pragma unroll
        for (int kt = 0; kt < 12; ++kt) {
            int c0 = kt * 16 + tg * 2;
            uint32_t a0 = ld_u32(xs + (rb + g) * XP + c0);
            uint32_t a1 = ld_u32(xs + (rb + g + 8) * XP + c0);
            uint32_t a2 = ld_u32(xs + (rb + g) * XP + c0 + 8);
            uint32_t a3 = ld_u32(xs + (rb + g + 8) * XP + c0 + 8);
#pragma unroll
            for (int nt = 0; nt < 4; ++nt) {
                const __nv_bfloat16* wp = ws + (cb + nt * 8 + g) * WP + c0;
                mma_bf16(acc[nt], a0, a1, a2, a3, ld_u32(wp), ld_u32(wp + 8));
            }
        }
#pragma unroll
        for (int nt = 0; nt < 4; ++nt) {
            int col = nc * 64 + cb + nt * 8 + tg * 2;
            float q0 = s_bq[col], q1 = s_bq[col + 1];
            *(uint32_t*)(qs + (rb + g) * QP + col)     = packbf(acc[nt][0] + q0, acc[nt][1] + q1);
            *(uint32_t*)(qs + (rb + g + 8) * QP + col) = packbf(acc[nt][2] + q0, acc[nt][3] + q1);
        }
        __syncthreads();
    }

    // ---------- phase 3: attention (2 heads in parallel, 3 iters) ----------
    const float scale = 0.1767766953f;  // 1/sqrt(32)
#pragma unroll 1
    for (int hi = 0; hi < 3; ++hi) {
        int head = hi * 2 + (warp >> 2);
        int qo = head * 32, ko = 192 + head * 32, vo = 384 + head * 32;
        float sacc[8][4];
#pragma unroll
        for (int nt = 0; nt < 8; ++nt)
#pragma unroll
            for (int e = 0; e < 4; ++e) sacc[nt][e] = 0.f;
        // S = Q @ K^T  (64x32 @ 32x64)
#pragma unroll
        for (int kt = 0; kt < 2; ++kt) {
            int c0 = kt * 16 + tg * 2;
            uint32_t a0 = ld_u32(qs + (rb + g) * QP + qo + c0);
            uint32_t a1 = ld_u32(qs + (rb + g + 8) * QP + qo + c0);
            uint32_t a2 = ld_u32(qs + (rb + g) * QP + qo + c0 + 8);
            uint32_t a3 = ld_u32(qs + (rb + g + 8) * QP + qo + c0 + 8);
#pragma unroll
            for (int nt = 0; nt < 8; ++nt) {
                const __nv_bfloat16* kp = qs + (nt * 8 + g) * QP + ko + c0;
                mma_bf16(sacc[nt], a0, a1, a2, a3, ld_u32(kp), ld_u32(kp + 8));
            }
        }
        // scale + mask cols>=49, row softmax (rows rb+g and rb+g+8)
        float mx0 = -1e30f, mx1 = -1e30f;
#pragma unroll
        for (int nt = 0; nt < 8; ++nt) {
            int col = nt * 8 + tg * 2;
#pragma unroll
            for (int e = 0; e < 2; ++e) {
                if (col + e >= LWIN) {
                    sacc[nt][e] = -1e30f; sacc[nt][2 + e] = -1e30f;
                } else {
                    sacc[nt][e]     *= scale;
                    sacc[nt][2 + e] *= scale;
                }
                mx0 = fmaxf(mx0, sacc[nt][e]);
                mx1 = fmaxf(mx1, sacc[nt][2 + e]);
            }
        }
        mx0 = fmaxf(mx0, __shfl_xor_sync(0xffffffffu, mx0, 1));
        mx0 = fmaxf(mx0, __shfl_xor_sync(0xffffffffu, mx0, 2));
        mx1 = fmaxf(mx1, __shfl_xor_sync(0xffffffffu, mx1, 1));
        mx1 = fmaxf(mx1, __shfl_xor_sync(0xffffffffu, mx1, 2));
        float sm0 = 0.f, sm1 = 0.f;
#pragma unroll
        for (int nt = 0; nt < 8; ++nt) {
#pragma unroll
            for (int e = 0; e < 2; ++e) {
                float p0 = __expf(sacc[nt][e] - mx0);
                float p1 = __expf(sacc[nt][2 + e] - mx1);
                sacc[nt][e] = p0; sacc[nt][2 + e] = p1;
                sm0 += p0; sm1 += p1;
            }
        }
        sm0 += __shfl_xor_sync(0xffffffffu, sm0, 1);
        sm0 += __shfl_xor_sync(0xffffffffu, sm0, 2);
        sm1 += __shfl_xor_sync(0xffffffffu, sm1, 1);
        sm1 += __shfl_xor_sync(0xffffffffu, sm1, 2);
        float i0 = 1.f / sm0, i1 = 1.f / sm1;
        // O = P @ V  (64x64 @ 64x32); P fragments come straight from sacc
        float oacc[4][4];
#pragma unroll
        for (int nt = 0; nt < 4; ++nt)
#pragma unroll
            for (int e = 0; e < 4; ++e) oacc[nt][e] = 0.f;
#pragma unroll
        for (int kt = 0; kt < 4; ++kt) {
            uint32_t pa0 = packbf(sacc[2 * kt][0] * i0, sacc[2 * kt][1] * i0);
            uint32_t pa1 = packbf(sacc[2 * kt][2] * i1, sacc[2 * kt][3] * i1);
            uint32_t pa2 = packbf(sacc[2 * kt + 1][0] * i0, sacc[2 * kt + 1][1] * i0);
            uint32_t pa3 = packbf(sacc[2 * kt + 1][2] * i1, sacc[2 * kt + 1][3] * i1);
            int kr = kt * 16 + tg * 2;
#pragma unroll
            for (int nt = 0; nt < 4; ++nt) {
                int ncol = vo + nt * 8 + g;
                const __nv_bfloat16* vp = qs + kr * QP + ncol;
                uint32_t bb0 = (uint32_t)(*(const unsigned short*)vp)
                             | ((uint32_t)(*(const unsigned short*)(vp + QP)) << 16);
                const __nv_bfloat16* vp2 = vp + 8 * QP;
                uint32_t bb1 = (uint32_t)(*(const unsigned short*)vp2)
                             | ((uint32_t)(*(const unsigned short*)(vp2 + QP)) << 16);
                mma_bf16(oacc[nt], pa0, pa1, pa2, pa3, bb0, bb1);
            }
        }
        // write head output into xs (reused as attn-out concat buffer)
#pragma unroll
        for (int nt = 0; nt < 4; ++nt) {
            int col = head * 32 + nt * 8 + tg * 2;
            *(uint32_t*)(xs + (rb + g) * XP + col)     = packbf(oacc[nt][0], oacc[nt][1]);
            *(uint32_t*)(xs + (rb + g + 8) * XP + col) = packbf(oacc[nt][2], oacc[nt][3]);
        }
    }
    __syncthreads();

    // ---------- phase 4: out-proj (64x192)@(192x192) + residual + scatter ----------
#pragma unroll 1
    for (int nc = 0; nc < 3; ++nc) {
        for (int idx = tid; idx < 1536; idx += 256) {
            int row = idx / 24, u = idx % 24;
            ((uint4*)(ws + row * WP))[u] =
                ((const uint4*)(g_wout + (nc * 64 + row) * 192))[u];
        }
        __syncthreads();
        float acc[4][4];
#pragma unroll
        for (int nt = 0; nt < 4; ++nt)
#pragma unroll
            for (int e = 0; e < 4; ++e) acc[nt][e] = 0.f;
#pragma unroll
        for (int kt = 0; kt < 12; ++kt) {
            int c0 = kt * 16 + tg * 2;
            uint32_t a0 = ld_u32(xs + (rb + g) * XP + c0);
            uint32_t a1 = ld_u32(xs + (rb + g + 8) * XP + c0);
            uint32_t a2 = ld_u32(xs + (rb + g) * XP + c0 + 8);
            uint32_t a3 = ld_u32(xs + (rb + g + 8) * XP + c0 + 8);
#pragma unroll
            for (int nt = 0; nt < 4; ++nt) {
                const __nv_bfloat16* wp = ws + (cb + nt * 8 + g) * WP + c0;
                mma_bf16(acc[nt], a0, a1, a2, a3, ld_u32(wp), ld_u32(wp + 8));
            }
        }
        int r0 = rb + g, r1 = rb + g + 8;
        long ro0 = (long)s_row[r0] * CHN;
        long ro1 = (long)s_row[r1] * CHN;
#pragma unroll
        for (int nt = 0; nt < 4; ++nt) {
            int col = nc * 64 + cb + nt * 8 + tg * 2;
            float bb0 = s_bo[col], bb1 = s_bo[col + 1];
            if (r0 < LWIN) {
                float2 sc = *(const float2*)(x + ro0 + col);
                float2 o = { acc[nt][0] + bb0 + sc.x, acc[nt][1] + bb1 + sc.y };
                *(float2*)(out + ro0 + col) = o;
            }
            if (r1 < LWIN) {
                float2 sc = *(const float2*)(x + ro1 + col);
                float2 o = { acc[nt][2] + bb0 + sc.x, acc[nt][3] + bb1 + sc.y };
                *(float2*)(out + ro1 + col) = o;
            }
        }
        __syncthreads();
    }
}

extern "C" void kernel_launch(void* const* d_in, const int* in_sizes, int n_in,
                              void* d_out, int out_size) {
    const float* x     = (const float*)d_in[0];
    const float* wqkv  = (const float*)d_in[1];
    const float* bqkv  = (const float*)d_in[2];
    const float* wout  = (const float*)d_in[3];
    const float* bout  = (const float*)d_in[4];
    const float* gamma = (const float*)d_in[5];
    const float* beta  = (const float*)d_in[6];
    float* out = (float*)d_out;

    prep_weights<<<(576 * 192 + 255) / 256, 256>>>(wqkv, wout);

    cudaFuncSetAttribute(swin_kernel,
                         cudaFuncAttributeMaxDynamicSharedMemorySize, SMEM_BYTES);
    swin_kernel<<<NWIN, 256, SMEM_BYTES>>>(x, bqkv, bout, gamma, beta, out);
}

// round 4
// speedup vs baseline: 1.7495x; 1.7495x over previous
#include <cuda_runtime.h>
#include <cuda_bf16.h>
#include <cstdint>

// Shifted-window attention block: B=16, H=W=112, C=192, heads=6, hd=32, WS=7, SHIFT=3.
// 112 % 7 == 0 -> no padding; roll+partition permutes tokens into 4096 windows x 49.
// One CTA per window, rows padded to 64. Per-head-pair fused pipeline:
//   LN -> { QKV(pair) -> attention(pair) } x3 -> out-proj + residual.
// GEMM warps are column slices (24 cols x 64 rows) so each weight fragment is
// loaded by exactly one warp directly from L2 (no smem staging).

#define CHN   192
#define LWIN  49
#define HWDIM 112
#define NPIX  (112*112)
#define NWIN  4096
#define XP    200    // pitch (bf16 elems) for xs / os / qk: conflict-free LDS.32 frags

// ---- persistent bf16 weight copies (converted once per launch) ----
__device__ __nv_bfloat16 g_wqkv[576 * 192];
__device__ __nv_bfloat16 g_wout[192 * 192];

__global__ void prep_weights(const float* __restrict__ wqkv,
                             const float* __restrict__ wout) {
    int i = blockIdx.x * 256 + threadIdx.x;
    if (i < 576 * 192) g_wqkv[i] = __float2bfloat16(wqkv[i]);
    if (i < 192 * 192) g_wout[i] = __float2bfloat16(wout[i]);
}

__device__ __forceinline__ uint32_t ld_u32(const __nv_bfloat16* p) {
    return *reinterpret_cast<const uint32_t*>(p);
}
// read-only path for weights (all CTAs share these lines)
__device__ __forceinline__ uint32_t ldg_u32(const __nv_bfloat16* p) {
    return __ldg(reinterpret_cast<const uint32_t*>(p));
}
__device__ __forceinline__ uint32_t packbf(float a, float b) {
    __nv_bfloat162 t = __floats2bfloat162_rn(a, b);
    return *reinterpret_cast<uint32_t*>(&t);
}
__device__ __forceinline__ void mma_bf16(float* c,
        uint32_t a0, uint32_t a1, uint32_t a2, uint32_t a3,
        uint32_t b0, uint32_t b1) {
    asm volatile(
        "mma.sync.aligned.m16n8k16.row.col.f32.bf16.bf16.f32 "
        "{%0,%1,%2,%3}, {%4,%5,%6,%7}, {%8,%9}, {%0,%1,%2,%3};\n"
        : "+f"(c[0]), "+f"(c[1]), "+f"(c[2]), "+f"(c[3])
        : "r"(a0), "r"(a1), "r"(a2), "r"(a3), "r"(b0), "r"(b1));
}

// smem layout (bytes): xs (LN output), os (attn output), qk (per-pair q|k|v)
#define OFF_XS   0
#define OFF_OS   25600      // 64*200*2
#define OFF_QK   51200
#define OFF_ROW  76800
#define SMEM_BYTES 77056

__global__ __launch_bounds__(256, 3) void swin_kernel(
    const float* __restrict__ x,
    const float* __restrict__ b_qkv,
    const float* __restrict__ b_out,
    const float* __restrict__ gamma,
    const float* __restrict__ beta,
    float* __restrict__ out)
{
    extern __shared__ unsigned char smem[];
    __nv_bfloat16* xs = (__nv_bfloat16*)(smem + OFF_XS);
    __nv_bfloat16* os = (__nv_bfloat16*)(smem + OFF_OS);
    __nv_bfloat16* qk = (__nv_bfloat16*)(smem + OFF_QK);
    int*           s_row = (int*)(smem + OFF_ROW);

    const int tid  = threadIdx.x;
    const int warp = tid >> 5, lane = tid & 31;
    const int g  = lane >> 2, tg = lane & 3;

    const int wi = blockIdx.x;
    const int bidx = wi >> 8;
    const int wh = (wi >> 4) & 15;
    const int ww = wi & 15;

    // ---------- phase 0: token gather offsets + zero pad rows ----------
    if (tid < 64) {
        int r = 0;
        if (tid < LWIN) {
            int ii = tid / 7, jj = tid % 7;
            int hh = wh * 7 + ii + 3; if (hh >= HWDIM) hh -= HWDIM;
            int cc = ww * 7 + jj + 3; if (cc >= HWDIM) cc -= HWDIM;
            r = bidx * NPIX + hh * HWDIM + cc;
        }
        s_row[tid] = r;
    }
    for (int i = tid; i < 15 * 96; i += 256) {
        int row = 49 + i / 96, cw = i % 96;
        ((uint32_t*)(xs + row * XP))[cw] = 0u;
    }
    __syncthreads();

    // ---------- phase 1: gather + LayerNorm -> xs (bf16) ----------
    {
        float gm[6], bt[6];
#pragma unroll
        for (int j = 0; j < 6; ++j) {
            gm[j] = gamma[lane + j * 32];
            bt[j] = beta[lane + j * 32];
        }
        for (int l = warp; l < LWIN; l += 8) {
            const float* xr = x + (long)s_row[l] * CHN;
            float v[6];
            float sum = 0.f, ssq = 0.f;
#pragma unroll
            for (int j = 0; j < 6; ++j) {
                v[j] = xr[lane + j * 32];
                sum += v[j]; ssq += v[j] * v[j];
            }
#pragma unroll
            for (int o = 16; o > 0; o >>= 1) {
                sum += __shfl_xor_sync(0xffffffffu, sum, o);
                ssq += __shfl_xor_sync(0xffffffffu, ssq, o);
            }
            float mu  = sum * (1.f / 192.f);
            float var = ssq * (1.f / 192.f) - mu * mu;
            float rs  = rsqrtf(var + 1e-5f);
#pragma unroll
            for (int j = 0; j < 6; ++j)
                xs[l * XP + lane + j * 32] =
                    __float2bfloat16((v[j] - mu) * rs * gm[j] + bt[j]);
        }
    }
    __syncthreads();

    // per-warp column-slice constants for QKV (24 cols per warp)
    const int cb0 = warp * 24;
    int wrowb[3], scol[3];
#pragma unroll
    for (int u = 0; u < 3; ++u) {
        int cbase = cb0 + u * 8;
        int s_ = cbase / 96;          // head parity within pair
        int r  = cbase % 96;
        int part = r / 32;            // 0=q 1=k 2=v
        int d0 = r % 32;              // dim within head
        wrowb[u] = part * 192 + s_ * 32 + d0;   // + hi*64 at use
        scol[u]  = part * 64  + s_ * 32 + d0;   // smem col in qk buffer
    }
    const int s_att = warp >> 2;            // attention head parity
    const int rb    = (warp & 3) * 16;      // attention row block
    const float scale = 0.1767766953f;      // 1/sqrt(32)

    // ---------- phase 2: per head-pair { QKV GEMM ; attention } ----------
#pragma unroll 1
    for (int hi = 0; hi < 3; ++hi) {
        // --- QKV GEMM: 64 rows x 24 cols per warp, weights direct from L2 ---
        float acc[3][4][4];
#pragma unroll
        for (int u = 0; u < 3; ++u)
#pragma unroll
            for (int rt = 0; rt < 4; ++rt)
#pragma unroll
                for (int e = 0; e < 4; ++e) acc[u][rt][e] = 0.f;
#pragma unroll
        for (int kt = 0; kt < 12; ++kt) {
            int c0 = kt * 16 + tg * 2;
            uint32_t b[3][2];
#pragma unroll
            for (int u = 0; u < 3; ++u) {
                const __nv_bfloat16* wp =
                    g_wqkv + (long)(wrowb[u] + hi * 64 + g) * 192 + c0;
                b[u][0] = ldg_u32(wp);
                b[u][1] = ldg_u32(wp + 8);
            }
#pragma unroll
            for (int rt = 0; rt < 4; ++rt) {
                const __nv_bfloat16* ap = xs + (rt * 16 + g) * XP + c0;
                uint32_t a0 = ld_u32(ap);
                uint32_t a1 = ld_u32(ap + 8 * XP);
                uint32_t a2 = ld_u32(ap + 8);
                uint32_t a3 = ld_u32(ap + 8 * XP + 8);
#pragma unroll
                for (int u = 0; u < 3; ++u)
                    mma_bf16(acc[u][rt], a0, a1, a2, a3, b[u][0], b[u][1]);
            }
        }
        // store q|k|v (+bias) into qk buffer
#pragma unroll
        for (int u = 0; u < 3; ++u) {
            float2 bias = *(const float2*)(b_qkv + wrowb[u] + hi * 64 + tg * 2);
            int sc = scol[u] + tg * 2;
#pragma unroll
            for (int rt = 0; rt < 4; ++rt) {
                *(uint32_t*)(qk + (rt * 16 + g) * XP + sc) =
                    packbf(acc[u][rt][0] + bias.x, acc[u][rt][1] + bias.y);
                *(uint32_t*)(qk + (rt * 16 + g + 8) * XP + sc) =
                    packbf(acc[u][rt][2] + bias.x, acc[u][rt][3] + bias.y);
            }
        }
        __syncthreads();

        // --- attention for head = hi*2 + s_att ---
        {
            const int qo = s_att * 32, ko = 64 + s_att * 32, vo = 128 + s_att * 32;
            const int head = hi * 2 + s_att;
            float sacc[8][4];
#pragma unroll
            for (int nt = 0; nt < 8; ++nt)
#pragma unroll
                for (int e = 0; e < 4; ++e) sacc[nt][e] = 0.f;
            // S = Q K^T (64x32 @ 32x64)
#pragma unroll
            for (int kt = 0; kt < 2; ++kt) {
                int c0 = kt * 16 + tg * 2;
                const __nv_bfloat16* qp = qk + (rb + g) * XP + qo + c0;
                uint32_t a0 = ld_u32(qp);
                uint32_t a1 = ld_u32(qp + 8 * XP);
                uint32_t a2 = ld_u32(qp + 8);
                uint32_t a3 = ld_u32(qp + 8 * XP + 8);
#pragma unroll
                for (int nt = 0; nt < 8; ++nt) {
                    const __nv_bfloat16* kp = qk + (nt * 8 + g) * XP + ko + c0;
                    mma_bf16(sacc[nt], a0, a1, a2, a3, ld_u32(kp), ld_u32(kp + 8));
                }
            }
            // scale + mask + softmax (rows rb+g, rb+g+8)
            float mx0 = -1e30f, mx1 = -1e30f;
#pragma unroll
            for (int nt = 0; nt < 8; ++nt) {
                int col = nt * 8 + tg * 2;
#pragma unroll
                for (int e = 0; e < 2; ++e) {
                    if (col + e >= LWIN) {
                        sacc[nt][e] = -1e30f; sacc[nt][2 + e] = -1e30f;
                    } else {
                        sacc[nt][e]     *= scale;
                        sacc[nt][2 + e] *= scale;
                    }
                    mx0 = fmaxf(mx0, sacc[nt][e]);
                    mx1 = fmaxf(mx1, sacc[nt][2 + e]);
                }
            }
            mx0 = fmaxf(mx0, __shfl_xor_sync(0xffffffffu, mx0, 1));
            mx0 = fmaxf(mx0, __shfl_xor_sync(0xffffffffu, mx0, 2));
            mx1 = fmaxf(mx1, __shfl_xor_sync(0xffffffffu, mx1, 1));
            mx1 = fmaxf(mx1, __shfl_xor_sync(0xffffffffu, mx1, 2));
            float sm0 = 0.f, sm1 = 0.f;
#pragma unroll
            for (int nt = 0; nt < 8; ++nt)
#pragma unroll
                for (int e = 0; e < 2; ++e) {
                    float p0 = __expf(sacc[nt][e] - mx0);
                    float p1 = __expf(sacc[nt][2 + e] - mx1);
                    sacc[nt][e] = p0; sacc[nt][2 + e] = p1;
                    sm0 += p0; sm1 += p1;
                }
            sm0 += __shfl_xor_sync(0xffffffffu, sm0, 1);
            sm0 += __shfl_xor_sync(0xffffffffu, sm0, 2);
            sm1 += __shfl_xor_sync(0xffffffffu, sm1, 1);
            sm1 += __shfl_xor_sync(0xffffffffu, sm1, 2);
            float i0 = 1.f / sm0, i1 = 1.f / sm1;
            // O = P V (64x64 @ 64x32)
            float oacc[4][4];
#pragma unroll
            for (int nt = 0; nt < 4; ++nt)
#pragma unroll
                for (int e = 0; e < 4; ++e) oacc[nt][e] = 0.f;
#pragma unroll
            for (int kt = 0; kt < 4; ++kt) {
                uint32_t pa0 = packbf(sacc[2 * kt][0] * i0, sacc[2 * kt][1] * i0);
                uint32_t pa1 = packbf(sacc[2 * kt][2] * i1, sacc[2 * kt][3] * i1);
                uint32_t pa2 = packbf(sacc[2 * kt + 1][0] * i0, sacc[2 * kt + 1][1] * i0);
                uint32_t pa3 = packbf(sacc[2 * kt + 1][2] * i1, sacc[2 * kt + 1][3] * i1);
                int kr = kt * 16 + tg * 2;
#pragma unroll
                for (int nt = 0; nt < 4; ++nt) {
                    const __nv_bfloat16* vp = qk + kr * XP + vo + nt * 8 + g;
                    uint32_t bb0 = (uint32_t)(*(const unsigned short*)vp)
                                 | ((uint32_t)(*(const unsigned short*)(vp + XP)) << 16);
                    const __nv_bfloat16* vp2 = vp + 8 * XP;
                    uint32_t bb1 = (uint32_t)(*(const unsigned short*)vp2)
                                 | ((uint32_t)(*(const unsigned short*)(vp2 + XP)) << 16);
                    mma_bf16(oacc[nt], pa0, pa1, pa2, pa3, bb0, bb1);
                }
            }
#pragma unroll
            for (int nt = 0; nt < 4; ++nt) {
                int col = head * 32 + nt * 8 + tg * 2;
                *(uint32_t*)(os + (rb + g) * XP + col)     = packbf(oacc[nt][0], oacc[nt][1]);
                *(uint32_t*)(os + (rb + g + 8) * XP + col) = packbf(oacc[nt][2], oacc[nt][3]);
            }
        }
        __syncthreads();
    }

    // ---------- phase 3: out-proj (64x192 @ 192x192) + residual + scatter ----------
    {
        float acc[3][4][4];
#pragma unroll
        for (int u = 0; u < 3; ++u)
#pragma unroll
            for (int rt = 0; rt < 4; ++rt)
#pragma unroll
                for (int e = 0; e < 4; ++e) acc[u][rt][e] = 0.f;
#pragma unroll
        for (int kt = 0; kt < 12; ++kt) {
            int c0 = kt * 16 + tg * 2;
            uint32_t b[3][2];
#pragma unroll
            for (int u = 0; u < 3; ++u) {
                const __nv_bfloat16* wp =
                    g_wout + (long)(cb0 + u * 8 + g) * 192 + c0;
                b[u][0] = ldg_u32(wp);
                b[u][1] = ldg_u32(wp + 8);
            }
#pragma unroll
            for (int rt = 0; rt < 4; ++rt) {
                const __nv_bfloat16* ap = os + (rt * 16 + g) * XP + c0;
                uint32_t a0 = ld_u32(ap);
                uint32_t a1 = ld_u32(ap + 8 * XP);
                uint32_t a2 = ld_u32(ap + 8);
                uint32_t a3 = ld_u32(ap + 8 * XP + 8);
#pragma unroll
                for (int u = 0; u < 3; ++u)
                    mma_bf16(acc[u][rt], a0, a1, a2, a3, b[u][0], b[u][1]);
            }
        }
#pragma unroll
        for (int u = 0; u < 3; ++u) {
            int col = cb0 + u * 8 + tg * 2;
            float2 bo = *(const float2*)(b_out + col);
#pragma unroll
            for (int rt = 0; rt < 4; ++rt) {
                int r0 = rt * 16 + g, r1 = r0 + 8;
                if (r0 < LWIN) {
                    long ro = (long)s_row[r0] * CHN;
                    float2 sc = *(const float2*)(x + ro + col);
                    float2 o = { acc[u][rt][0] + bo.x + sc.x,
                                 acc[u][rt][1] + bo.y + sc.y };
                    *(float2*)(out + ro + col) = o;
                }
                if (r1 < LWIN) {
                    long ro = (long)s_row[r1] * CHN;
                    float2 sc = *(const float2*)(x + ro + col);
                    float2 o = { acc[u][rt][2] + bo.x + sc.x,
                                 acc[u][rt][3] + bo.y + sc.y };
                    *(float2*)(out + ro + col) = o;
                }
            }
        }
    }
}

extern "C" void kernel_launch(void* const* d_in, const int* in_sizes, int n_in,
                              void* d_out, int out_size) {
    const float* x     = (const float*)d_in[0];
    const float* wqkv  = (const float*)d_in[1];
    const float* bqkv  = (const float*)d_in[2];
    const float* wout  = (const float*)d_in[3];
    const float* bout  = (const float*)d_in[4];
    const float* gamma = (const float*)d_in[5];
    const float* beta  = (const float*)d_in[6];
    float* out = (float*)d_out;

    prep_weights<<<(576 * 192 + 255) / 256, 256>>>(wqkv, wout);

    cudaFuncSetAttribute(swin_kernel,
                         cudaFuncAttributeMaxDynamicSharedMemorySize, SMEM_BYTES);
    swin_kernel<<<NWIN, 256, SMEM_BYTES>>>(x, bqkv, bout, gamma, beta, out);
}

// round 6
// speedup vs baseline: 2.9579x; 1.6907x over previous
#include <cuda_runtime.h>
#include <cuda_bf16.h>
#include <cstdint>

// Shifted-window attention block: B=16, H=W=112, C=192, heads=6, hd=32, WS=7, SHIFT=3.
// One CTA per window (4096 windows x 49 tokens, rows padded to 64).
// Pipeline: LN -> { QKV(head-pair) -> attention(pair) } x3 -> out-proj + residual.
// Weights are pre-packed in mma-B-fragment order so each warp's B-load is one
// fully-coalesced 256B LDG.64 (lane l reads bytes l*8..l*8+7).

#define CHN   192
#define LWIN  49
#define HWDIM 112
#define NPIX  (112*112)
#define NWIN  4096
#define XP    200    // pitch (bf16 elems): 400B/row -> conflict-free LDS frag loads

// ---- fragment-packed bf16 weights, built once per launch ----
// layout: [nb][kt][lane][4] bf16, nb = out-col block of 8, kt = k block of 16,
// lane = g*4+tg; 4 bf16 = {k0,k1,k8,k9} of (row nb*8+g, col kt*16+tg*2).
__device__ __nv_bfloat16 g_wqkv[576 * 192];
__device__ __nv_bfloat16 g_wout[192 * 192];

__global__ void prep_weights(const float* __restrict__ wqkv,
                             const float* __restrict__ wout) {
    int i = blockIdx.x * 256 + threadIdx.x;
    if (i < 576 * 192) {
        int j    = i & 3;
        int lane = (i >> 2) & 31;
        int kt   = (i >> 7) % 12;
        int nb   = (i >> 7) / 12;
        int gg = lane >> 2, tt = lane & 3;
        int row = nb * 8 + gg;
        int col = kt * 16 + tt * 2 + ((j >> 1) << 3) + (j & 1);
        g_wqkv[i] = __float2bfloat16(wqkv[row * 192 + col]);
    }
    if (i < 192 * 192) {
        int j    = i & 3;
        int lane = (i >> 2) & 31;
        int kt   = (i >> 7) % 12;
        int nb   = (i >> 7) / 12;
        int gg = lane >> 2, tt = lane & 3;
        int row = nb * 8 + gg;
        int col = kt * 16 + tt * 2 + ((j >> 1) << 3) + (j & 1);
        g_wout[i] = __float2bfloat16(wout[row * 192 + col]);
    }
}

__device__ __forceinline__ uint32_t ld_u32(const __nv_bfloat16* p) {
    return *reinterpret_cast<const uint32_t*>(p);
}
__device__ __forceinline__ uint32_t packbf(float a, float b) {
    __nv_bfloat162 t = __floats2bfloat162_rn(a, b);
    return *reinterpret_cast<uint32_t*>(&t);
}
__device__ __forceinline__ void mma_bf16(float* c,
        uint32_t a0, uint32_t a1, uint32_t a2, uint32_t a3,
        uint32_t b0, uint32_t b1) {
    asm volatile(
        "mma.sync.aligned.m16n8k16.row.col.f32.bf16.bf16.f32 "
        "{%0,%1,%2,%3}, {%4,%5,%6,%7}, {%8,%9}, {%0,%1,%2,%3};\n"
        : "+f"(c[0]), "+f"(c[1]), "+f"(c[2]), "+f"(c[3])
        : "r"(a0), "r"(a1), "r"(a2), "r"(a3), "r"(b0), "r"(b1));
}

// smem layout (bytes): xs (LN output), os (attn output), qk (per-pair q|k|v)
#define OFF_XS   0
#define OFF_OS   25600      // 64*200*2
#define OFF_QK   51200
#define OFF_ROW  76800
#define SMEM_BYTES 77056

__global__ __launch_bounds__(256, 2) void swin_kernel(
    const float* __restrict__ x,
    const float* __restrict__ b_qkv,
    const float* __restrict__ b_out,
    const float* __restrict__ gamma,
    const float* __restrict__ beta,
    float* __restrict__ out)
{
    extern __shared__ unsigned char smem[];
    __nv_bfloat16* xs = (__nv_bfloat16*)(smem + OFF_XS);
    __nv_bfloat16* os = (__nv_bfloat16*)(smem + OFF_OS);
    __nv_bfloat16* qk = (__nv_bfloat16*)(smem + OFF_QK);
    int*           s_row = (int*)(smem + OFF_ROW);

    const int tid  = threadIdx.x;
    const int warp = tid >> 5, lane = tid & 31;
    const int g  = lane >> 2, tg = lane & 3;

    const int wi = blockIdx.x;
    const int bidx = wi >> 8;
    const int wh = (wi >> 4) & 15;
    const int ww = wi & 15;

    // ---------- phase 0: token gather offsets + zero pad rows ----------
    if (tid < 64) {
        int r = 0;
        if (tid < LWIN) {
            int ii = tid / 7, jj = tid % 7;
            int hh = wh * 7 + ii + 3; if (hh >= HWDIM) hh -= HWDIM;
            int cc = ww * 7 + jj + 3; if (cc >= HWDIM) cc -= HWDIM;
            r = bidx * NPIX + hh * HWDIM + cc;
        }
        s_row[tid] = r;
    }
    for (int i = tid; i < 15 * 96; i += 256) {
        int row = 49 + i / 96, cw = i % 96;
        ((uint32_t*)(xs + row * XP))[cw] = 0u;
    }
    __syncthreads();

    // ---------- phase 1: gather + LayerNorm -> xs (bf16) ----------
    {
        float gm[6], bt[6];
#pragma unroll
        for (int j = 0; j < 6; ++j) {
            gm[j] = gamma[lane + j * 32];
            bt[j] = beta[lane + j * 32];
        }
        for (int l = warp; l < LWIN; l += 8) {
            const float* xr = x + (long)s_row[l] * CHN;
            float v[6];
            float sum = 0.f, ssq = 0.f;
#pragma unroll
            for (int j = 0; j < 6; ++j) {
                v[j] = xr[lane + j * 32];
                sum += v[j]; ssq += v[j] * v[j];
            }
#pragma unroll
            for (int o = 16; o > 0; o >>= 1) {
                sum += __shfl_xor_sync(0xffffffffu, sum, o);
                ssq += __shfl_xor_sync(0xffffffffu, ssq, o);
            }
            float mu  = sum * (1.f / 192.f);
            float var = ssq * (1.f / 192.f) - mu * mu;
            float rs  = rsqrtf(var + 1e-5f);
#pragma unroll
            for (int j = 0; j < 6; ++j)
                xs[l * XP + lane + j * 32] =
                    __float2bfloat16((v[j] - mu) * rs * gm[j] + bt[j]);
        }
    }
    __syncthreads();

    // per-warp column-slice constants for QKV (24 cols per warp)
    const int cb0 = warp * 24;
    int wrowb[3], wrow8[3], scol[3];
#pragma unroll
    for (int u = 0; u < 3; ++u) {
        int cbase = cb0 + u * 8;
        int s_ = cbase / 96;          // head parity within pair
        int r  = cbase % 96;
        int part = r / 32;            // 0=q 1=k 2=v
        int d0 = r % 32;              // dim within head
        wrowb[u] = part * 192 + s_ * 32 + d0;   // + hi*64 at use (bias index)
        wrow8[u] = wrowb[u] >> 3;               // n-block; + hi*8 at use
        scol[u]  = part * 64  + s_ * 32 + d0;   // smem col in qk buffer
    }
    const int s_att = warp >> 2;            // attention head parity
    const int rb    = (warp & 3) * 16;      // attention row block
    const float scale = 0.1767766953f;      // 1/sqrt(32)
    const uint2* wq = (const uint2*)g_wqkv;
    const uint2* wo = (const uint2*)g_wout;

    // ---------- phase 2: per head-pair { QKV GEMM ; attention } ----------
#pragma unroll 1
    for (int hi = 0; hi < 3; ++hi) {
        // --- QKV GEMM: 64 rows x 24 cols per warp, packed weights from L2 ---
        float acc[3][4][4];
#pragma unroll
        for (int u = 0; u < 3; ++u)
#pragma unroll
            for (int rt = 0; rt < 4; ++rt)
#pragma unroll
                for (int e = 0; e < 4; ++e) acc[u][rt][e] = 0.f;
#pragma unroll
        for (int kt = 0; kt < 12; ++kt) {
            uint2 b[3];
#pragma unroll
            for (int u = 0; u < 3; ++u) {
                int nb = wrow8[u] + hi * 8;
                b[u] = __ldg(wq + ((nb * 12 + kt) * 32 + lane));
            }
            int c0 = kt * 16 + tg * 2;
#pragma unroll
            for (int rt = 0; rt < 4; ++rt) {
                const __nv_bfloat16* ap = xs + (rt * 16 + g) * XP + c0;
                uint32_t a0 = ld_u32(ap);
                uint32_t a1 = ld_u32(ap + 8 * XP);
                uint32_t a2 = ld_u32(ap + 8);
                uint32_t a3 = ld_u32(ap + 8 * XP + 8);
#pragma unroll
                for (int u = 0; u < 3; ++u)
                    mma_bf16(acc[u][rt], a0, a1, a2, a3, b[u].x, b[u].y);
            }
        }
        // store q|k|v (+bias) into qk buffer
#pragma unroll
        for (int u = 0; u < 3; ++u) {
            float2 bias = *(const float2*)(b_qkv + wrowb[u] + hi * 64 + tg * 2);
            int sc = scol[u] + tg * 2;
#pragma unroll
            for (int rt = 0; rt < 4; ++rt) {
                *(uint32_t*)(qk + (rt * 16 + g) * XP + sc) =
                    packbf(acc[u][rt][0] + bias.x, acc[u][rt][1] + bias.y);
                *(uint32_t*)(qk + (rt * 16 + g + 8) * XP + sc) =
                    packbf(acc[u][rt][2] + bias.x, acc[u][rt][3] + bias.y);
            }
        }
        __syncthreads();

        // --- attention for head = hi*2 + s_att ---
        {
            const int qo = s_att * 32, ko = 64 + s_att * 32, vo = 128 + s_att * 32;
            const int head = hi * 2 + s_att;
            float sacc[8][4];
#pragma unroll
            for (int nt = 0; nt < 8; ++nt)
#pragma unroll
                for (int e = 0; e < 4; ++e) sacc[nt][e] = 0.f;
            // S = Q K^T (64x32 @ 32x64)
#pragma unroll
            for (int kt = 0; kt < 2; ++kt) {
                int c0 = kt * 16 + tg * 2;
                const __nv_bfloat16* qp = qk + (rb + g) * XP + qo + c0;
                uint32_t a0 = ld_u32(qp);
                uint32_t a1 = ld_u32(qp + 8 * XP);
                uint32_t a2 = ld_u32(qp + 8);
                uint32_t a3 = ld_u32(qp + 8 * XP + 8);
#pragma unroll
                for (int nt = 0; nt < 8; ++nt) {
                    const __nv_bfloat16* kp = qk + (nt * 8 + g) * XP + ko + c0;
                    mma_bf16(sacc[nt], a0, a1, a2, a3, ld_u32(kp), ld_u32(kp + 8));
                }
            }
            // scale + mask + softmax (rows rb+g, rb+g+8)
            float mx0 = -1e30f, mx1 = -1e30f;
#pragma unroll
            for (int nt = 0; nt < 8; ++nt) {
                int col = nt * 8 + tg * 2;
#pragma unroll
                for (int e = 0; e < 2; ++e) {
                    if (col + e >= LWIN) {
                        sacc[nt][e] = -1e30f; sacc[nt][2 + e] = -1e30f;
                    } else {
                        sacc[nt][e]     *= scale;
                        sacc[nt][2 + e] *= scale;
                    }
                    mx0 = fmaxf(mx0, sacc[nt][e]);
                    mx1 = fmaxf(mx1, sacc[nt][2 + e]);
                }
            }
            mx0 = fmaxf(mx0, __shfl_xor_sync(0xffffffffu, mx0, 1));
            mx0 = fmaxf(mx0, __shfl_xor_sync(0xffffffffu, mx0, 2));
            mx1 = fmaxf(mx1, __shfl_xor_sync(0xffffffffu, mx1, 1));
            mx1 = fmaxf(mx1, __shfl_xor_sync(0xffffffffu, mx1, 2));
            float sm0 = 0.f, sm1 = 0.f;
#pragma unroll
            for (int nt = 0; nt < 8; ++nt)
#pragma unroll
                for (int e = 0; e < 2; ++e) {
                    float p0 = __expf(sacc[nt][e] - mx0);
                    float p1 = __expf(sacc[nt][2 + e] - mx1);
                    sacc[nt][e] = p0; sacc[nt][2 + e] = p1;
                    sm0 += p0; sm1 += p1;
                }
            sm0 += __shfl_xor_sync(0xffffffffu, sm0, 1);
            sm0 += __shfl_xor_sync(0xffffffffu, sm0, 2);
            sm1 += __shfl_xor_sync(0xffffffffu, sm1, 1);
            sm1 += __shfl_xor_sync(0xffffffffu, sm1, 2);
            float i0 = 1.f / sm0, i1 = 1.f / sm1;
            // O = P V (64x64 @ 64x32)
            float oacc[4][4];
#pragma unroll
            for (int nt = 0; nt < 4; ++nt)
#pragma unroll
                for (int e = 0; e < 4; ++e) oacc[nt][e] = 0.f;
#pragma unroll
            for (int kt = 0; kt < 4; ++kt) {
                uint32_t pa0 = packbf(sacc[2 * kt][0] * i0, sacc[2 * kt][1] * i0);
                uint32_t pa1 = packbf(sacc[2 * kt][2] * i1, sacc[2 * kt][3] * i1);
                uint32_t pa2 = packbf(sacc[2 * kt + 1][0] * i0, sacc[2 * kt + 1][1] * i0);
                uint32_t pa3 = packbf(sacc[2 * kt + 1][2] * i1, sacc[2 * kt + 1][3] * i1);
                int kr = kt * 16 + tg * 2;
#pragma unroll
                for (int nt = 0; nt < 4; ++nt) {
                    const __nv_bfloat16* vp = qk + kr * XP + vo + nt * 8 + g;
                    uint32_t bb0 = (uint32_t)(*(const unsigned short*)vp)
                                 | ((uint32_t)(*(const unsigned short*)(vp + XP)) << 16);
                    const __nv_bfloat16* vp2 = vp + 8 * XP;
                    uint32_t bb1 = (uint32_t)(*(const unsigned short*)vp2)
                                 | ((uint32_t)(*(const unsigned short*)(vp2 + XP)) << 16);
                    mma_bf16(oacc[nt], pa0, pa1, pa2, pa3, bb0, bb1);
                }
            }
#pragma unroll
            for (int nt = 0; nt < 4; ++nt) {
                int col = head * 32 + nt * 8 + tg * 2;
                *(uint32_t*)(os + (rb + g) * XP + col)     = packbf(oacc[nt][0], oacc[nt][1]);
                *(uint32_t*)(os + (rb + g + 8) * XP + col) = packbf(oacc[nt][2], oacc[nt][3]);
            }
        }
        __syncthreads();
    }

    // ---------- phase 3: out-proj (64x192 @ 192x192) + residual + scatter ----------
    {
        float acc[3][4][4];
#pragma unroll
        for (int u = 0; u < 3; ++u)
#pragma unroll
            for (int rt = 0; rt < 4; ++rt)
#pragma unroll
                for (int e = 0; e < 4; ++e) acc[u][rt][e] = 0.f;
#pragma unroll
        for (int kt = 0; kt < 12; ++kt) {
            uint2 b[3];
#pragma unroll
            for (int u = 0; u < 3; ++u) {
                int nb = warp * 3 + u;
                b[u] = __ldg(wo + ((nb * 12 + kt) * 32 + lane));
            }
            int c0 = kt * 16 + tg * 2;
#pragma unroll
            for (int rt = 0; rt < 4; ++rt) {
                const __nv_bfloat16* ap = os + (rt * 16 + g) * XP + c0;
                uint32_t a0 = ld_u32(ap);
                uint32_t a1 = ld_u32(ap + 8 * XP);
                uint32_t a2 = ld_u32(ap + 8);
                uint32_t a3 = ld_u32(ap + 8 * XP + 8);
#pragma unroll
                for (int u = 0; u < 3; ++u)
                    mma_bf16(acc[u][rt], a0, a1, a2, a3, b[u].x, b[u].y);
            }
        }
#pragma unroll
        for (int u = 0; u < 3; ++u) {
            int col = cb0 + u * 8 + tg * 2;
            float2 bo = *(const float2*)(b_out + col);
#pragma unroll
            for (int rt = 0; rt < 4; ++rt) {
                int r0 = rt * 16 + g, r1 = r0 + 8;
                if (r0 < LWIN) {
                    long ro = (long)s_row[r0] * CHN;
                    float2 sc = *(const float2*)(x + ro + col);
                    float2 o = { acc[u][rt][0] + bo.x + sc.x,
                                 acc[u][rt][1] + bo.y + sc.y };
                    *(float2*)(out + ro + col) = o;
                }
                if (r1 < LWIN) {
                    long ro = (long)s_row[r1] * CHN;
                    float2 sc = *(const float2*)(x + ro + col);
                    float2 o = { acc[u][rt][2] + bo.x + sc.x,
                                 acc[u][rt][3] + bo.y + sc.y };
                    *(float2*)(out + ro + col) = o;
                }
            }
        }
    }
}

extern "C" void kernel_launch(void* const* d_in, const int* in_sizes, int n_in,
                              void* d_out, int out_size) {
    const float* x     = (const float*)d_in[0];
    const float* wqkv  = (const float*)d_in[1];
    const float* bqkv  = (const float*)d_in[2];
    const float* wout  = (const float*)d_in[3];
    const float* bout  = (const float*)d_in[4];
    const float* gamma = (const float*)d_in[5];
    const float* beta  = (const float*)d_in[6];
    float* out = (float*)d_out;

    prep_weights<<<(576 * 192 + 255) / 256, 256>>>(wqkv, wout);

    cudaFuncSetAttribute(swin_kernel,
                         cudaFuncAttributeMaxDynamicSharedMemorySize, SMEM_BYTES);
    swin_kernel<<<NWIN, 256, SMEM_BYTES>>>(x, bqkv, bout, gamma, beta, out);
}